// round 11
// baseline (speedup 1.0000x reference)
#include <cuda_runtime.h>
#include <cuda_bf16.h>
#include <cuda_fp16.h>

#define N_NODES 50000
#define E_EDGES 800000
#define D 64
#define NC 40
#define RB 128            // rows per block in GEMM kernels
#define NPB 16            // nodes per block in aggregation

// Scratch (allocation-free rule: __device__ globals).
__device__ __align__(16) float  g_dinv[N_NODES];
__device__ __align__(16) __half g_hsh[N_NODES * D];   // fp16 pre-scaled features
__device__ __align__(16) float  g_agg[N_NODES * D];   // fp32 agg (seeded with self term)
__device__ int g_cnt   [N_NODES];
__device__ int g_rowptr[N_NODES + 1];
__device__ int g_cursor[N_NODES];
__device__ int g_eid   [E_EDGES];                     // CSR column indices (src ids)

// ---------------------------------------------------------------------------
// CSR build: count -> scan (rowptr/cursor/dinv) -> fill
// ---------------------------------------------------------------------------
__global__ void k_zero_cnt() {
    int i = blockIdx.x * blockDim.x + threadIdx.x;
    if (i < N_NODES) g_cnt[i] = 0;
}

__global__ void k_count(const int* __restrict__ dst) {
    int e = blockIdx.x * blockDim.x + threadIdx.x;
    if (e < E_EDGES) atomicAdd(&g_cnt[dst[e]], 1);
}

__global__ void k_scan() {
    __shared__ int s[1024];
    const int PER = (N_NODES + 1023) / 1024;   // 49
    int t = threadIdx.x;
    int base = t * PER;
    int sum = 0;
    #pragma unroll 4
    for (int i = 0; i < PER; i++) {
        int idx = base + i;
        if (idx < N_NODES) sum += g_cnt[idx];
    }
    s[t] = sum;
    __syncthreads();
    for (int off = 1; off < 1024; off <<= 1) {
        int v = (t >= off) ? s[t - off] : 0;
        __syncthreads();
        s[t] += v;
        __syncthreads();
    }
    int run = s[t] - sum;
    #pragma unroll 4
    for (int i = 0; i < PER; i++) {
        int idx = base + i;
        if (idx < N_NODES) {
            g_rowptr[idx] = run;
            g_cursor[idx] = run;
            int c = g_cnt[idx];
            g_dinv[idx] = rsqrtf((float)(c + 1));   // +1 self-loop
            run += c;
        }
    }
    if (t == 0) g_rowptr[N_NODES] = E_EDGES;
}

__global__ void k_fill(const int* __restrict__ src, const int* __restrict__ dst) {
    int e = blockIdx.x * blockDim.x + threadIdx.x;
    if (e < E_EDGES) {
        int p = atomicAdd(&g_cursor[dst[e]], 1);
        g_eid[p] = src[e];
    }
}

// ---------------------------------------------------------------------------
// Store helper: fp32 self-loop seed into agg, fp16 copy for gathers
// ---------------------------------------------------------------------------
__device__ __forceinline__ void store_scaled(int row, int c4, float4 v) {
    *reinterpret_cast<float4*>(g_agg + (size_t)row * D + c4) = v;
    __half2 h01 = __floats2half2_rn(v.x, v.y);
    __half2 h23 = __floats2half2_rn(v.z, v.w);
    uint2 packed;
    packed.x = *reinterpret_cast<unsigned*>(&h01);
    packed.y = *reinterpret_cast<unsigned*>(&h23);
    *reinterpret_cast<uint2*>(g_hsh + (size_t)row * D + c4) = packed;
}

__device__ __forceinline__ void acc_half4(float4& acc, uint2 p) {
    __half2 a = *reinterpret_cast<__half2*>(&p.x);
    __half2 b = *reinterpret_cast<__half2*>(&p.y);
    float2 fa = __half22float2(a);
    float2 fb = __half22float2(b);
    acc.x += fa.x; acc.y += fa.y; acc.z += fb.x; acc.w += fb.y;
}

// ---------------------------------------------------------------------------
// Layer-1 GEMM: hs = (x @ W1) * dinv[row]; agg = hs (fp32); hsh = hs (fp16)
// ---------------------------------------------------------------------------
__global__ void k_gemm1(const float* __restrict__ x, const float* __restrict__ W1) {
    __shared__ float sW[D][D];
    __shared__ float sx[RB][D];
    int tid = threadIdx.x;
    int row0 = blockIdx.x * RB;

    #pragma unroll
    for (int i = 0; i < 4; i++) {
        int idx = tid * 4 + i * 1024;
        *reinterpret_cast<float4*>(&sW[0][0] + idx) =
            *reinterpret_cast<const float4*>(W1 + idx);
    }
    #pragma unroll
    for (int i = 0; i < 8; i++) {
        int lin = tid + i * 256;
        int r = lin >> 4;
        int c4 = (lin & 15) * 4;
        int row = row0 + r;
        float4 v = make_float4(0.f, 0.f, 0.f, 0.f);
        if (row < N_NODES) v = *reinterpret_cast<const float4*>(x + (size_t)row * D + c4);
        *reinterpret_cast<float4*>(&sx[r][c4]) = v;
    }
    __syncthreads();

    int tc = tid & 15;
    int tr = tid >> 4;
    float4 acc[8];
    #pragma unroll
    for (int i = 0; i < 8; i++) acc[i] = make_float4(0.f, 0.f, 0.f, 0.f);
    #pragma unroll
    for (int k = 0; k < D; k++) {
        float4 w = *reinterpret_cast<float4*>(&sW[k][tc * 4]);
        #pragma unroll
        for (int i = 0; i < 8; i++) {
            float xv = sx[tr * 8 + i][k];
            acc[i].x = fmaf(xv, w.x, acc[i].x);
            acc[i].y = fmaf(xv, w.y, acc[i].y);
            acc[i].z = fmaf(xv, w.z, acc[i].z);
            acc[i].w = fmaf(xv, w.w, acc[i].w);
        }
    }
    #pragma unroll
    for (int i = 0; i < 8; i++) {
        int row = row0 + tr * 8 + i;
        if (row < N_NODES) {
            float di = g_dinv[row];
            store_scaled(row, tc * 4,
                make_float4(acc[i].x * di, acc[i].y * di, acc[i].z * di, acc[i].w * di));
        }
    }
}

// ---------------------------------------------------------------------------
// CSR gather aggregation: agg[n] (pre-seeded with self) += sum hsh[nbr]
// 16 lanes/node; neighbor loop unrolled x8 -> 8 independent coalesced gathers.
// ---------------------------------------------------------------------------
__global__ void k_agg() {
    int tid = threadIdx.x;
    int node = blockIdx.x * NPB + (tid >> 4);
    int lane = tid & 15;
    if (node >= N_NODES) return;
    const uint2* hsh2 = reinterpret_cast<const uint2*>(g_hsh);
    float4*      agg4 = reinterpret_cast<float4*>(g_agg);

    float4 acc = agg4[(size_t)node * 16 + lane];   // fp32 self-loop seed
    int j   = g_rowptr[node];
    int end = g_rowptr[node + 1];

    for (; j + 8 <= end; j += 8) {
        int s[8];
        #pragma unroll
        for (int i = 0; i < 8; i++) s[i] = g_eid[j + i];      // uniform broadcast
        uint2 p[8];
        #pragma unroll
        for (int i = 0; i < 8; i++) p[i] = hsh2[(size_t)s[i] * 16 + lane];  // MLP=8
        #pragma unroll
        for (int i = 0; i < 8; i++) acc_half4(acc, p[i]);
    }
    for (; j + 2 <= end; j += 2) {
        int s0 = g_eid[j], s1 = g_eid[j + 1];
        uint2 p0 = hsh2[(size_t)s0 * 16 + lane];
        uint2 p1 = hsh2[(size_t)s1 * 16 + lane];
        acc_half4(acc, p0);
        acc_half4(acc, p1);
    }
    if (j < end) {
        uint2 p0 = hsh2[(size_t)g_eid[j] * 16 + lane];
        acc_half4(acc, p0);
    }
    agg4[(size_t)node * 16 + lane] = acc;
}

// ---------------------------------------------------------------------------
// Fused: h1 = tanh(agg * dinv + b1); hs = (h1 @ W2) * dinv; agg/hsh = hs
// ---------------------------------------------------------------------------
__global__ void k_layer2(const float* __restrict__ W2, const float* __restrict__ b1) {
    __shared__ float sW[D][D];
    __shared__ float st[RB][D];
    int tid = threadIdx.x;
    int row0 = blockIdx.x * RB;

    #pragma unroll
    for (int i = 0; i < 4; i++) {
        int idx = tid * 4 + i * 1024;
        *reinterpret_cast<float4*>(&sW[0][0] + idx) =
            *reinterpret_cast<const float4*>(W2 + idx);
    }
    #pragma unroll
    for (int i = 0; i < 8; i++) {
        int lin = tid + i * 256;
        int r = lin >> 4;
        int c4 = (lin & 15) * 4;
        int row = row0 + r;
        float4 v = make_float4(0.f, 0.f, 0.f, 0.f);
        if (row < N_NODES) {
            float di = g_dinv[row];
            float4 a = *reinterpret_cast<const float4*>(g_agg + (size_t)row * D + c4);
            float4 b = *reinterpret_cast<const float4*>(b1 + c4);
            v.x = tanhf(fmaf(a.x, di, b.x));
            v.y = tanhf(fmaf(a.y, di, b.y));
            v.z = tanhf(fmaf(a.z, di, b.z));
            v.w = tanhf(fmaf(a.w, di, b.w));
        }
        *reinterpret_cast<float4*>(&st[r][c4]) = v;
    }
    __syncthreads();

    int tc = tid & 15;
    int tr = tid >> 4;
    float4 acc[8];
    #pragma unroll
    for (int i = 0; i < 8; i++) acc[i] = make_float4(0.f, 0.f, 0.f, 0.f);
    #pragma unroll
    for (int k = 0; k < D; k++) {
        float4 w = *reinterpret_cast<float4*>(&sW[k][tc * 4]);
        #pragma unroll
        for (int i = 0; i < 8; i++) {
            float xv = st[tr * 8 + i][k];
            acc[i].x = fmaf(xv, w.x, acc[i].x);
            acc[i].y = fmaf(xv, w.y, acc[i].y);
            acc[i].z = fmaf(xv, w.z, acc[i].z);
            acc[i].w = fmaf(xv, w.w, acc[i].w);
        }
    }
    #pragma unroll
    for (int i = 0; i < 8; i++) {
        int row = row0 + tr * 8 + i;
        if (row < N_NODES) {
            float di = g_dinv[row];
            store_scaled(row, tc * 4,
                make_float4(acc[i].x * di, acc[i].y * di, acc[i].z * di, acc[i].w * di));
        }
    }
}

// ---------------------------------------------------------------------------
// Fused final: h = tanh(agg * dinv + b2)  -> d_out[N*NC ..]  (h output)
//              out = h @ Wc + bc          -> d_out[0 .. N*NC) (logits)
// ---------------------------------------------------------------------------
__global__ void k_final(const float* __restrict__ Wc, const float* __restrict__ b2,
                        const float* __restrict__ bc, float* __restrict__ out) {
    __shared__ float sW[D][NC];
    __shared__ float st[RB][D];
    int tid = threadIdx.x;
    int row0 = blockIdx.x * RB;

    #pragma unroll
    for (int i = 0; i < 3; i++) {
        int f4 = tid + i * 256;
        if (f4 < D * NC / 4)
            *(reinterpret_cast<float4*>(&sW[0][0]) + f4) =
                *(reinterpret_cast<const float4*>(Wc) + f4);
    }
    #pragma unroll
    for (int i = 0; i < 8; i++) {
        int lin = tid + i * 256;
        int r = lin >> 4;
        int c4 = (lin & 15) * 4;
        int row = row0 + r;
        float4 v = make_float4(0.f, 0.f, 0.f, 0.f);
        if (row < N_NODES) {
            float di = g_dinv[row];
            float4 a = *reinterpret_cast<const float4*>(g_agg + (size_t)row * D + c4);
            float4 b = *reinterpret_cast<const float4*>(b2 + c4);
            v.x = tanhf(fmaf(a.x, di, b.x));
            v.y = tanhf(fmaf(a.y, di, b.y));
            v.z = tanhf(fmaf(a.z, di, b.z));
            v.w = tanhf(fmaf(a.w, di, b.w));
            *reinterpret_cast<float4*>(out + (size_t)N_NODES * NC + (size_t)row * D + c4) = v;
        }
        *reinterpret_cast<float4*>(&st[r][c4]) = v;
    }
    __syncthreads();

    int tc = tid & 15;
    int tr = tid >> 4;
    if (tc < NC / 4) {
        float4 bcv = *reinterpret_cast<const float4*>(bc + tc * 4);
        float4 acc[8];
        #pragma unroll
        for (int i = 0; i < 8; i++) acc[i] = bcv;
        #pragma unroll
        for (int k = 0; k < D; k++) {
            float4 w = *reinterpret_cast<float4*>(&sW[k][tc * 4]);
            #pragma unroll
            for (int i = 0; i < 8; i++) {
                float xv = st[tr * 8 + i][k];
                acc[i].x = fmaf(xv, w.x, acc[i].x);
                acc[i].y = fmaf(xv, w.y, acc[i].y);
                acc[i].z = fmaf(xv, w.z, acc[i].z);
                acc[i].w = fmaf(xv, w.w, acc[i].w);
            }
        }
        #pragma unroll
        for (int i = 0; i < 8; i++) {
            int row = row0 + tr * 8 + i;
            if (row < N_NODES)
                *reinterpret_cast<float4*>(out + (size_t)row * NC + tc * 4) = acc[i];
        }
    }
}

// ---------------------------------------------------------------------------
extern "C" void kernel_launch(void* const* d_in, const int* in_sizes, int n_in,
                              void* d_out, int out_size) {
    const float* x   = (const float*)d_in[0];
    const int*   ei  = (const int*)d_in[1];   // [2, E] int32 (JAX x64 disabled)
    const float* W1  = (const float*)d_in[2];
    const float* b1  = (const float*)d_in[3];
    const float* W2  = (const float*)d_in[4];
    const float* b2  = (const float*)d_in[5];
    const float* Wc  = (const float*)d_in[6];
    const float* bc  = (const float*)d_in[7];
    float* out = (float*)d_out;

    const int* src = ei;              // edge_index[0]
    const int* dst = ei + E_EDGES;    // edge_index[1]

    const int TB = 256;
    const int gN    = (N_NODES + TB - 1) / TB;
    const int gE    = (E_EDGES + TB - 1) / TB;
    const int gRows = (N_NODES + RB - 1) / RB;            // 391
    const int gAgg  = (N_NODES + NPB - 1) / NPB;          // 3125

    // CSR build + dinv
    k_zero_cnt<<<gN, TB>>>();
    k_count   <<<gE, TB>>>(dst);
    k_scan    <<<1, 1024>>>();
    k_fill    <<<gE, TB>>>(src, dst);

    // Layer pipeline
    k_gemm1  <<<gRows, TB>>>(x, W1);
    k_agg    <<<gAgg, TB>>>();
    k_layer2 <<<gRows, TB>>>(W2, b1);
    k_agg    <<<gAgg, TB>>>();
    k_final  <<<gRows, TB>>>(Wc, b2, bc, out);
}

// round 12
// speedup vs baseline: 2.2695x; 2.2695x over previous
#include <cuda_runtime.h>
#include <cuda_bf16.h>
#include <cuda_fp16.h>

#define N_NODES 50000
#define E_EDGES 800000
#define D 64
#define NC 40
#define RB 128            // rows per block in GEMM kernels

// Scratch (allocation-free rule: __device__ globals).
__device__ int g_cnt[N_NODES];                        // in-degree (excl self)
__device__ __align__(16) __half g_hsh[N_NODES * D];   // fp16 pre-scaled features
__device__ __align__(16) float  g_agg[N_NODES * D];   // fp32 agg (seeded with self term)

__device__ __forceinline__ float node_dinv(int row) {
    return rsqrtf((float)(g_cnt[row] + 1));           // +1 self-loop
}

// ---------------------------------------------------------------------------
// Degree count (g_cnt zeroed by cudaMemsetAsync in kernel_launch)
// ---------------------------------------------------------------------------
__global__ void k_count(const int* __restrict__ dst) {
    int e = blockIdx.x * blockDim.x + threadIdx.x;
    if (e < E_EDGES) atomicAdd(&g_cnt[dst[e]], 1);
}

// ---------------------------------------------------------------------------
// Store helper: fp32 self-loop seed into agg, fp16 copy for scatter gathers
// ---------------------------------------------------------------------------
__device__ __forceinline__ void store_scaled(int row, int c4, float4 v) {
    *reinterpret_cast<float4*>(g_agg + (size_t)row * D + c4) = v;
    __half2 h01 = __floats2half2_rn(v.x, v.y);
    __half2 h23 = __floats2half2_rn(v.z, v.w);
    uint2 packed;
    packed.x = *reinterpret_cast<unsigned*>(&h01);
    packed.y = *reinterpret_cast<unsigned*>(&h23);
    *reinterpret_cast<uint2*>(g_hsh + (size_t)row * D + c4) = packed;
}

// 8x4 register tile MAC over one k-block of 4 (vectorized LDS: 12 LDS.128 / 128 FMA)
__device__ __forceinline__ void mac_k4(const float (*sW)[D], const float (*sX)[D],
                                       int k4, int tr, int tc, float4 acc[8]) {
    float4 w0 = *reinterpret_cast<const float4*>(&sW[k4 * 4 + 0][tc * 4]);
    float4 w1 = *reinterpret_cast<const float4*>(&sW[k4 * 4 + 1][tc * 4]);
    float4 w2 = *reinterpret_cast<const float4*>(&sW[k4 * 4 + 2][tc * 4]);
    float4 w3 = *reinterpret_cast<const float4*>(&sW[k4 * 4 + 3][tc * 4]);
    #pragma unroll
    for (int i = 0; i < 8; i++) {
        float4 xv = *reinterpret_cast<const float4*>(&sX[tr * 8 + i][k4 * 4]);
        acc[i].x = fmaf(xv.x, w0.x, acc[i].x); acc[i].y = fmaf(xv.x, w0.y, acc[i].y);
        acc[i].z = fmaf(xv.x, w0.z, acc[i].z); acc[i].w = fmaf(xv.x, w0.w, acc[i].w);
        acc[i].x = fmaf(xv.y, w1.x, acc[i].x); acc[i].y = fmaf(xv.y, w1.y, acc[i].y);
        acc[i].z = fmaf(xv.y, w1.z, acc[i].z); acc[i].w = fmaf(xv.y, w1.w, acc[i].w);
        acc[i].x = fmaf(xv.z, w2.x, acc[i].x); acc[i].y = fmaf(xv.z, w2.y, acc[i].y);
        acc[i].z = fmaf(xv.z, w2.z, acc[i].z); acc[i].w = fmaf(xv.z, w2.w, acc[i].w);
        acc[i].x = fmaf(xv.w, w3.x, acc[i].x); acc[i].y = fmaf(xv.w, w3.y, acc[i].y);
        acc[i].z = fmaf(xv.w, w3.z, acc[i].z); acc[i].w = fmaf(xv.w, w3.w, acc[i].w);
    }
}

// ---------------------------------------------------------------------------
// Layer-1 GEMM: hs = (x @ W1) * dinv[row]; agg = hs (fp32); hsh = hs (fp16)
// ---------------------------------------------------------------------------
__global__ void __launch_bounds__(256) k_gemm1(const float* __restrict__ x,
                                               const float* __restrict__ W1) {
    __shared__ float sW[D][D];
    __shared__ float sx[RB][D];
    int tid = threadIdx.x;
    int row0 = blockIdx.x * RB;

    #pragma unroll
    for (int i = 0; i < 4; i++) {
        int idx = tid * 4 + i * 1024;
        *reinterpret_cast<float4*>(&sW[0][0] + idx) =
            *reinterpret_cast<const float4*>(W1 + idx);
    }
    #pragma unroll
    for (int i = 0; i < 8; i++) {
        int lin = tid + i * 256;
        int r = lin >> 4;
        int c4 = (lin & 15) * 4;
        int row = row0 + r;
        float4 v = make_float4(0.f, 0.f, 0.f, 0.f);
        if (row < N_NODES) v = *reinterpret_cast<const float4*>(x + (size_t)row * D + c4);
        *reinterpret_cast<float4*>(&sx[r][c4]) = v;
    }
    __syncthreads();

    int tc = tid & 15;
    int tr = tid >> 4;
    float4 acc[8];
    #pragma unroll
    for (int i = 0; i < 8; i++) acc[i] = make_float4(0.f, 0.f, 0.f, 0.f);
    #pragma unroll
    for (int k4 = 0; k4 < D / 4; k4++) mac_k4(sW, sx, k4, tr, tc, acc);

    #pragma unroll
    for (int i = 0; i < 8; i++) {
        int row = row0 + tr * 8 + i;
        if (row < N_NODES) {
            float di = node_dinv(row);
            store_scaled(row, tc * 4,
                make_float4(acc[i].x * di, acc[i].y * di, acc[i].z * di, acc[i].w * di));
        }
    }
}

// ---------------------------------------------------------------------------
// Edge scatter: agg[dst] += hsh[src] (fp16 gather, fp32 float4 atomic).
// 16 lanes/edge: each gathers 4 halfs (8B, coalesced 128B/edge) -> 1 atomic.
// ---------------------------------------------------------------------------
__global__ void k_scatter(const int* __restrict__ src,
                          const int* __restrict__ dst) {
    long long idx = (long long)blockIdx.x * blockDim.x + threadIdx.x;
    int e = (int)(idx >> 4);
    int c = (int)(idx & 15);
    if (e >= E_EDGES) return;
    int s = src[e];
    int d = dst[e];
    uint2 p = reinterpret_cast<const uint2*>(g_hsh + (size_t)s * D)[c];
    __half2 h01 = *reinterpret_cast<__half2*>(&p.x);
    __half2 h23 = *reinterpret_cast<__half2*>(&p.y);
    float2 fa = __half22float2(h01);
    float2 fb = __half22float2(h23);
    atomicAdd(reinterpret_cast<float4*>(g_agg + (size_t)d * D) + c,
              make_float4(fa.x, fa.y, fb.x, fb.y));
}

// ---------------------------------------------------------------------------
// Fused: h1 = tanh(agg * dinv + b1); hs = (h1 @ W2) * dinv; agg/hsh = hs
// ---------------------------------------------------------------------------
__global__ void __launch_bounds__(256) k_layer2(const float* __restrict__ W2,
                                                const float* __restrict__ b1) {
    __shared__ float sW[D][D];
    __shared__ float st[RB][D];
    int tid = threadIdx.x;
    int row0 = blockIdx.x * RB;

    #pragma unroll
    for (int i = 0; i < 4; i++) {
        int idx = tid * 4 + i * 1024;
        *reinterpret_cast<float4*>(&sW[0][0] + idx) =
            *reinterpret_cast<const float4*>(W2 + idx);
    }
    #pragma unroll
    for (int i = 0; i < 8; i++) {
        int lin = tid + i * 256;
        int r = lin >> 4;
        int c4 = (lin & 15) * 4;
        int row = row0 + r;
        float4 v = make_float4(0.f, 0.f, 0.f, 0.f);
        if (row < N_NODES) {
            float di = node_dinv(row);
            float4 a = *reinterpret_cast<const float4*>(g_agg + (size_t)row * D + c4);
            float4 b = *reinterpret_cast<const float4*>(b1 + c4);
            v.x = tanhf(fmaf(a.x, di, b.x));
            v.y = tanhf(fmaf(a.y, di, b.y));
            v.z = tanhf(fmaf(a.z, di, b.z));
            v.w = tanhf(fmaf(a.w, di, b.w));
        }
        *reinterpret_cast<float4*>(&st[r][c4]) = v;
    }
    __syncthreads();

    int tc = tid & 15;
    int tr = tid >> 4;
    float4 acc[8];
    #pragma unroll
    for (int i = 0; i < 8; i++) acc[i] = make_float4(0.f, 0.f, 0.f, 0.f);
    #pragma unroll
    for (int k4 = 0; k4 < D / 4; k4++) mac_k4(sW, st, k4, tr, tc, acc);

    #pragma unroll
    for (int i = 0; i < 8; i++) {
        int row = row0 + tr * 8 + i;
        if (row < N_NODES) {
            float di = node_dinv(row);
            store_scaled(row, tc * 4,
                make_float4(acc[i].x * di, acc[i].y * di, acc[i].z * di, acc[i].w * di));
        }
    }
}

// ---------------------------------------------------------------------------
// Fused final: h = tanh(agg * dinv + b2)  -> d_out[N*NC ..]  (h output)
//              out = h @ Wc + bc          -> d_out[0 .. N*NC) (logits)
// ---------------------------------------------------------------------------
__global__ void __launch_bounds__(256) k_final(const float* __restrict__ Wc,
                                               const float* __restrict__ b2,
                                               const float* __restrict__ bc,
                                               float* __restrict__ out) {
    __shared__ float sW[D][NC];
    __shared__ float st[RB][D];
    int tid = threadIdx.x;
    int row0 = blockIdx.x * RB;

    #pragma unroll
    for (int i = 0; i < 3; i++) {
        int f4 = tid + i * 256;
        if (f4 < D * NC / 4)
            *(reinterpret_cast<float4*>(&sW[0][0]) + f4) =
                *(reinterpret_cast<const float4*>(Wc) + f4);
    }
    #pragma unroll
    for (int i = 0; i < 8; i++) {
        int lin = tid + i * 256;
        int r = lin >> 4;
        int c4 = (lin & 15) * 4;
        int row = row0 + r;
        float4 v = make_float4(0.f, 0.f, 0.f, 0.f);
        if (row < N_NODES) {
            float di = node_dinv(row);
            float4 a = *reinterpret_cast<const float4*>(g_agg + (size_t)row * D + c4);
            float4 b = *reinterpret_cast<const float4*>(b2 + c4);
            v.x = tanhf(fmaf(a.x, di, b.x));
            v.y = tanhf(fmaf(a.y, di, b.y));
            v.z = tanhf(fmaf(a.z, di, b.z));
            v.w = tanhf(fmaf(a.w, di, b.w));
            *reinterpret_cast<float4*>(out + (size_t)N_NODES * NC + (size_t)row * D + c4) = v;
        }
        *reinterpret_cast<float4*>(&st[r][c4]) = v;
    }
    __syncthreads();

    int tc = tid & 15;
    int tr = tid >> 4;
    if (tc < NC / 4) {
        float4 bcv = *reinterpret_cast<const float4*>(bc + tc * 4);
        float4 acc[8];
        #pragma unroll
        for (int i = 0; i < 8; i++) acc[i] = bcv;
        #pragma unroll
        for (int k4 = 0; k4 < D / 4; k4++) {
            float4 w0 = *reinterpret_cast<float4*>(&sW[k4 * 4 + 0][tc * 4]);
            float4 w1 = *reinterpret_cast<float4*>(&sW[k4 * 4 + 1][tc * 4]);
            float4 w2 = *reinterpret_cast<float4*>(&sW[k4 * 4 + 2][tc * 4]);
            float4 w3 = *reinterpret_cast<float4*>(&sW[k4 * 4 + 3][tc * 4]);
            #pragma unroll
            for (int i = 0; i < 8; i++) {
                float4 xv = *reinterpret_cast<float4*>(&st[tr * 8 + i][k4 * 4]);
                acc[i].x = fmaf(xv.x, w0.x, acc[i].x); acc[i].y = fmaf(xv.x, w0.y, acc[i].y);
                acc[i].z = fmaf(xv.x, w0.z, acc[i].z); acc[i].w = fmaf(xv.x, w0.w, acc[i].w);
                acc[i].x = fmaf(xv.y, w1.x, acc[i].x); acc[i].y = fmaf(xv.y, w1.y, acc[i].y);
                acc[i].z = fmaf(xv.y, w1.z, acc[i].z); acc[i].w = fmaf(xv.y, w1.w, acc[i].w);
                acc[i].x = fmaf(xv.z, w2.x, acc[i].x); acc[i].y = fmaf(xv.z, w2.y, acc[i].y);
                acc[i].z = fmaf(xv.z, w2.z, acc[i].z); acc[i].w = fmaf(xv.z, w2.w, acc[i].w);
                acc[i].x = fmaf(xv.w, w3.x, acc[i].x); acc[i].y = fmaf(xv.w, w3.y, acc[i].y);
                acc[i].z = fmaf(xv.w, w3.z, acc[i].z); acc[i].w = fmaf(xv.w, w3.w, acc[i].w);
            }
        }
        #pragma unroll
        for (int i = 0; i < 8; i++) {
            int row = row0 + tr * 8 + i;
            if (row < N_NODES)
                *reinterpret_cast<float4*>(out + (size_t)row * NC + tc * 4) = acc[i];
        }
    }
}

// ---------------------------------------------------------------------------
extern "C" void kernel_launch(void* const* d_in, const int* in_sizes, int n_in,
                              void* d_out, int out_size) {
    const float* x   = (const float*)d_in[0];
    const int*   ei  = (const int*)d_in[1];   // [2, E] int32 (JAX x64 disabled)
    const float* W1  = (const float*)d_in[2];
    const float* b1  = (const float*)d_in[3];
    const float* W2  = (const float*)d_in[4];
    const float* b2  = (const float*)d_in[5];
    const float* Wc  = (const float*)d_in[6];
    const float* bc  = (const float*)d_in[7];
    float* out = (float*)d_out;

    const int* src = ei;              // edge_index[0]
    const int* dst = ei + E_EDGES;    // edge_index[1]

    const int TB = 256;
    const int gE    = (E_EDGES + TB - 1) / TB;
    const int gRows = (N_NODES + RB - 1) / RB;            // 391
    const long long scatterThreads = (long long)E_EDGES * 16;
    const int gScat = (int)((scatterThreads + TB - 1) / TB);

    // Zero degree counts (capturable memset node), then count
    void* cnt_ptr = nullptr;
    cudaGetSymbolAddress(&cnt_ptr, g_cnt);
    cudaMemsetAsync(cnt_ptr, 0, N_NODES * sizeof(int));
    k_count<<<gE, TB>>>(dst);

    k_gemm1   <<<gRows, TB>>>(x, W1);
    k_scatter <<<gScat, TB>>>(src, dst);
    k_layer2  <<<gRows, TB>>>(W2, b1);
    k_scatter <<<gScat, TB>>>(src, dst);
    k_final   <<<gRows, TB>>>(Wc, b2, bc, out);
}

// round 13
// speedup vs baseline: 2.3721x; 1.0452x over previous
#include <cuda_runtime.h>
#include <cuda_bf16.h>
#include <cuda_fp16.h>

#define N_NODES 50000
#define E_EDGES 800000
#define D 64
#define NC 40
#define RB 128            // rows per block in GEMM kernels

typedef unsigned long long u64;

// Scratch (allocation-free rule: __device__ globals).
__device__ int g_cnt[N_NODES];                        // in-degree (excl self)
__device__ __align__(16) float  g_dinv[N_NODES];      // rsqrt(deg+1)
__device__ __align__(16) __half g_hsh[N_NODES * D];   // fp16 pre-scaled features
__device__ __align__(16) float  g_agg[N_NODES * D];   // fp32 agg (seeded with self term)

// ---- f32x2 packed helpers (FFMA2: 2 fp32 FMAs / instruction) -------------
__device__ __forceinline__ u64 pack2(float lo, float hi) {
    u64 r; asm("mov.b64 %0, {%1, %2};" : "=l"(r) : "f"(lo), "f"(hi)); return r;
}
__device__ __forceinline__ u64 dup2(float v) { return pack2(v, v); }
__device__ __forceinline__ void unpack2(u64 p, float& lo, float& hi) {
    asm("mov.b64 {%0, %1}, %2;" : "=f"(lo), "=f"(hi) : "l"(p));
}
__device__ __forceinline__ void fma2(u64& d, u64 a, u64 b) {
    asm("fma.rn.f32x2 %0, %1, %2, %0;" : "+l"(d) : "l"(a), "l"(b));
}
__device__ __forceinline__ float tanh_fast(float x) {
    float y; asm("tanh.approx.f32 %0, %1;" : "=f"(y) : "f"(x)); return y;
}

// ---------------------------------------------------------------------------
// Degree count (g_cnt zeroed by cudaMemsetAsync), then dinv = rsqrt(cnt+1)
// ---------------------------------------------------------------------------
__global__ void k_count(const int* __restrict__ dst) {
    int e = blockIdx.x * blockDim.x + threadIdx.x;
    if (e < E_EDGES) atomicAdd(&g_cnt[dst[e]], 1);
}
__global__ void k_finish_dinv() {
    int i = blockIdx.x * blockDim.x + threadIdx.x;
    if (i < N_NODES) g_dinv[i] = rsqrtf((float)(g_cnt[i] + 1));
}

// ---------------------------------------------------------------------------
// Store helper: fp32 self-loop seed into agg, fp16 copy for scatter gathers
// ---------------------------------------------------------------------------
__device__ __forceinline__ void store_scaled(int row, int c4, float4 v) {
    *reinterpret_cast<float4*>(g_agg + (size_t)row * D + c4) = v;
    __half2 h01 = __floats2half2_rn(v.x, v.y);
    __half2 h23 = __floats2half2_rn(v.z, v.w);
    uint2 packed;
    packed.x = *reinterpret_cast<unsigned*>(&h01);
    packed.y = *reinterpret_cast<unsigned*>(&h23);
    *reinterpret_cast<uint2*>(g_hsh + (size_t)row * D + c4) = packed;
}

// 8 rows x 4 cols tile MAC over one k-block of 4, using f32x2 packed FMA.
__device__ __forceinline__ void mac_k4_f32x2(const float (*sW)[D], const float (*sX)[D],
                                             int k4, int tr, int tc,
                                             u64 acc01[8], u64 acc23[8]) {
    float4 w0 = *reinterpret_cast<const float4*>(&sW[k4 * 4 + 0][tc * 4]);
    float4 w1 = *reinterpret_cast<const float4*>(&sW[k4 * 4 + 1][tc * 4]);
    float4 w2 = *reinterpret_cast<const float4*>(&sW[k4 * 4 + 2][tc * 4]);
    float4 w3 = *reinterpret_cast<const float4*>(&sW[k4 * 4 + 3][tc * 4]);
    u64 w0a = pack2(w0.x, w0.y), w0b = pack2(w0.z, w0.w);
    u64 w1a = pack2(w1.x, w1.y), w1b = pack2(w1.z, w1.w);
    u64 w2a = pack2(w2.x, w2.y), w2b = pack2(w2.z, w2.w);
    u64 w3a = pack2(w3.x, w3.y), w3b = pack2(w3.z, w3.w);
    #pragma unroll
    for (int i = 0; i < 8; i++) {
        float4 xv = *reinterpret_cast<const float4*>(&sX[tr * 8 + i][k4 * 4]);
        u64 x0 = dup2(xv.x), x1 = dup2(xv.y), x2 = dup2(xv.z), x3 = dup2(xv.w);
        fma2(acc01[i], x0, w0a); fma2(acc23[i], x0, w0b);
        fma2(acc01[i], x1, w1a); fma2(acc23[i], x1, w1b);
        fma2(acc01[i], x2, w2a); fma2(acc23[i], x2, w2b);
        fma2(acc01[i], x3, w3a); fma2(acc23[i], x3, w3b);
    }
}

// ---------------------------------------------------------------------------
// Layer-1 GEMM: hs = (x @ W1) * dinv[row]; agg = hs (fp32); hsh = hs (fp16)
// ---------------------------------------------------------------------------
__global__ void __launch_bounds__(256) k_gemm1(const float* __restrict__ x,
                                               const float* __restrict__ W1) {
    __shared__ float sW[D][D];
    __shared__ float sx[RB][D];
    int tid = threadIdx.x;
    int row0 = blockIdx.x * RB;

    #pragma unroll
    for (int i = 0; i < 4; i++) {
        int idx = tid * 4 + i * 1024;
        *reinterpret_cast<float4*>(&sW[0][0] + idx) =
            *reinterpret_cast<const float4*>(W1 + idx);
    }
    #pragma unroll
    for (int i = 0; i < 8; i++) {
        int lin = tid + i * 256;
        int r = lin >> 4;
        int c4 = (lin & 15) * 4;
        int row = row0 + r;
        float4 v = make_float4(0.f, 0.f, 0.f, 0.f);
        if (row < N_NODES) v = *reinterpret_cast<const float4*>(x + (size_t)row * D + c4);
        *reinterpret_cast<float4*>(&sx[r][c4]) = v;
    }
    __syncthreads();

    int tc = tid & 15;
    int tr = tid >> 4;
    u64 acc01[8], acc23[8];
    #pragma unroll
    for (int i = 0; i < 8; i++) { acc01[i] = 0ull; acc23[i] = 0ull; }
    #pragma unroll
    for (int k4 = 0; k4 < D / 4; k4++) mac_k4_f32x2(sW, sx, k4, tr, tc, acc01, acc23);

    #pragma unroll
    for (int i = 0; i < 8; i++) {
        int row = row0 + tr * 8 + i;
        if (row < N_NODES) {
            float di = g_dinv[row];
            float a0, a1, a2, a3;
            unpack2(acc01[i], a0, a1);
            unpack2(acc23[i], a2, a3);
            store_scaled(row, tc * 4, make_float4(a0 * di, a1 * di, a2 * di, a3 * di));
        }
    }
}

// ---------------------------------------------------------------------------
// Edge scatter: agg[dst] += hsh[src] (fp16 gather, fp32 float4 atomic).
// ---------------------------------------------------------------------------
__global__ void k_scatter(const int* __restrict__ src,
                          const int* __restrict__ dst) {
    long long idx = (long long)blockIdx.x * blockDim.x + threadIdx.x;
    int e = (int)(idx >> 4);
    int c = (int)(idx & 15);
    if (e >= E_EDGES) return;
    int s = src[e];
    int d = dst[e];
    uint2 p = reinterpret_cast<const uint2*>(g_hsh + (size_t)s * D)[c];
    __half2 h01 = *reinterpret_cast<__half2*>(&p.x);
    __half2 h23 = *reinterpret_cast<__half2*>(&p.y);
    float2 fa = __half22float2(h01);
    float2 fb = __half22float2(h23);
    atomicAdd(reinterpret_cast<float4*>(g_agg + (size_t)d * D) + c,
              make_float4(fa.x, fa.y, fb.x, fb.y));
}

// ---------------------------------------------------------------------------
// Fused: h1 = tanh(agg * dinv + b1); hs = (h1 @ W2) * dinv; agg/hsh = hs
// ---------------------------------------------------------------------------
__global__ void __launch_bounds__(256) k_layer2(const float* __restrict__ W2,
                                                const float* __restrict__ b1) {
    __shared__ float sW[D][D];
    __shared__ float st[RB][D];
    int tid = threadIdx.x;
    int row0 = blockIdx.x * RB;

    #pragma unroll
    for (int i = 0; i < 4; i++) {
        int idx = tid * 4 + i * 1024;
        *reinterpret_cast<float4*>(&sW[0][0] + idx) =
            *reinterpret_cast<const float4*>(W2 + idx);
    }
    #pragma unroll
    for (int i = 0; i < 8; i++) {
        int lin = tid + i * 256;
        int r = lin >> 4;
        int c4 = (lin & 15) * 4;
        int row = row0 + r;
        float4 v = make_float4(0.f, 0.f, 0.f, 0.f);
        if (row < N_NODES) {
            float di = g_dinv[row];
            float4 a = *reinterpret_cast<const float4*>(g_agg + (size_t)row * D + c4);
            float4 b = *reinterpret_cast<const float4*>(b1 + c4);
            v.x = tanh_fast(fmaf(a.x, di, b.x));
            v.y = tanh_fast(fmaf(a.y, di, b.y));
            v.z = tanh_fast(fmaf(a.z, di, b.z));
            v.w = tanh_fast(fmaf(a.w, di, b.w));
        }
        *reinterpret_cast<float4*>(&st[r][c4]) = v;
    }
    __syncthreads();

    int tc = tid & 15;
    int tr = tid >> 4;
    u64 acc01[8], acc23[8];
    #pragma unroll
    for (int i = 0; i < 8; i++) { acc01[i] = 0ull; acc23[i] = 0ull; }
    #pragma unroll
    for (int k4 = 0; k4 < D / 4; k4++) mac_k4_f32x2(sW, st, k4, tr, tc, acc01, acc23);

    #pragma unroll
    for (int i = 0; i < 8; i++) {
        int row = row0 + tr * 8 + i;
        if (row < N_NODES) {
            float di = g_dinv[row];
            float a0, a1, a2, a3;
            unpack2(acc01[i], a0, a1);
            unpack2(acc23[i], a2, a3);
            store_scaled(row, tc * 4, make_float4(a0 * di, a1 * di, a2 * di, a3 * di));
        }
    }
}

// ---------------------------------------------------------------------------
// Fused final: h = tanh(agg * dinv + b2)  -> d_out[N*NC ..]  (h output)
//              out = h @ Wc + bc          -> d_out[0 .. N*NC) (logits)
// ---------------------------------------------------------------------------
__global__ void __launch_bounds__(256) k_final(const float* __restrict__ Wc,
                                               const float* __restrict__ b2,
                                               const float* __restrict__ bc,
                                               float* __restrict__ out) {
    __shared__ float sW[D][NC];
    __shared__ float st[RB][D];
    int tid = threadIdx.x;
    int row0 = blockIdx.x * RB;

    #pragma unroll
    for (int i = 0; i < 3; i++) {
        int f4 = tid + i * 256;
        if (f4 < D * NC / 4)
            *(reinterpret_cast<float4*>(&sW[0][0]) + f4) =
                *(reinterpret_cast<const float4*>(Wc) + f4);
    }
    #pragma unroll
    for (int i = 0; i < 8; i++) {
        int lin = tid + i * 256;
        int r = lin >> 4;
        int c4 = (lin & 15) * 4;
        int row = row0 + r;
        float4 v = make_float4(0.f, 0.f, 0.f, 0.f);
        if (row < N_NODES) {
            float di = g_dinv[row];
            float4 a = *reinterpret_cast<const float4*>(g_agg + (size_t)row * D + c4);
            float4 b = *reinterpret_cast<const float4*>(b2 + c4);
            v.x = tanh_fast(fmaf(a.x, di, b.x));
            v.y = tanh_fast(fmaf(a.y, di, b.y));
            v.z = tanh_fast(fmaf(a.z, di, b.z));
            v.w = tanh_fast(fmaf(a.w, di, b.w));
            *reinterpret_cast<float4*>(out + (size_t)N_NODES * NC + (size_t)row * D + c4) = v;
        }
        *reinterpret_cast<float4*>(&st[r][c4]) = v;
    }
    __syncthreads();

    int tc = tid & 15;
    int tr = tid >> 4;
    if (tc < NC / 4) {
        float4 bcv = *reinterpret_cast<const float4*>(bc + tc * 4);
        u64 acc01[8], acc23[8];
        #pragma unroll
        for (int i = 0; i < 8; i++) {
            acc01[i] = pack2(bcv.x, bcv.y);
            acc23[i] = pack2(bcv.z, bcv.w);
        }
        #pragma unroll
        for (int k4 = 0; k4 < D / 4; k4++) {
            float4 w0 = *reinterpret_cast<float4*>(&sW[k4 * 4 + 0][tc * 4]);
            float4 w1 = *reinterpret_cast<float4*>(&sW[k4 * 4 + 1][tc * 4]);
            float4 w2 = *reinterpret_cast<float4*>(&sW[k4 * 4 + 2][tc * 4]);
            float4 w3 = *reinterpret_cast<float4*>(&sW[k4 * 4 + 3][tc * 4]);
            u64 w0a = pack2(w0.x, w0.y), w0b = pack2(w0.z, w0.w);
            u64 w1a = pack2(w1.x, w1.y), w1b = pack2(w1.z, w1.w);
            u64 w2a = pack2(w2.x, w2.y), w2b = pack2(w2.z, w2.w);
            u64 w3a = pack2(w3.x, w3.y), w3b = pack2(w3.z, w3.w);
            #pragma unroll
            for (int i = 0; i < 8; i++) {
                float4 xv = *reinterpret_cast<float4*>(&st[tr * 8 + i][k4 * 4]);
                u64 x0 = dup2(xv.x), x1 = dup2(xv.y), x2 = dup2(xv.z), x3 = dup2(xv.w);
                fma2(acc01[i], x0, w0a); fma2(acc23[i], x0, w0b);
                fma2(acc01[i], x1, w1a); fma2(acc23[i], x1, w1b);
                fma2(acc01[i], x2, w2a); fma2(acc23[i], x2, w2b);
                fma2(acc01[i], x3, w3a); fma2(acc23[i], x3, w3b);
            }
        }
        #pragma unroll
        for (int i = 0; i < 8; i++) {
            int row = row0 + tr * 8 + i;
            if (row < N_NODES) {
                float a0, a1, a2, a3;
                unpack2(acc01[i], a0, a1);
                unpack2(acc23[i], a2, a3);
                *reinterpret_cast<float4*>(out + (size_t)row * NC + tc * 4) =
                    make_float4(a0, a1, a2, a3);
            }
        }
    }
}

// ---------------------------------------------------------------------------
extern "C" void kernel_launch(void* const* d_in, const int* in_sizes, int n_in,
                              void* d_out, int out_size) {
    const float* x   = (const float*)d_in[0];
    const int*   ei  = (const int*)d_in[1];   // [2, E] int32 (JAX x64 disabled)
    const float* W1  = (const float*)d_in[2];
    const float* b1  = (const float*)d_in[3];
    const float* W2  = (const float*)d_in[4];
    const float* b2  = (const float*)d_in[5];
    const float* Wc  = (const float*)d_in[6];
    const float* bc  = (const float*)d_in[7];
    float* out = (float*)d_out;

    const int* src = ei;              // edge_index[0]
    const int* dst = ei + E_EDGES;    // edge_index[1]

    const int TB = 256;
    const int gN    = (N_NODES + TB - 1) / TB;
    const int gE    = (E_EDGES + TB - 1) / TB;
    const int gRows = (N_NODES + RB - 1) / RB;            // 391
    const long long scatterThreads = (long long)E_EDGES * 16;
    const int gScat = (int)((scatterThreads + TB - 1) / TB);

    void* cnt_ptr = nullptr;
    cudaGetSymbolAddress(&cnt_ptr, g_cnt);
    cudaMemsetAsync(cnt_ptr, 0, N_NODES * sizeof(int));
    k_count      <<<gE, TB>>>(dst);
    k_finish_dinv<<<gN, TB>>>();

    k_gemm1   <<<gRows, TB>>>(x, W1);
    k_scatter <<<gScat, TB>>>(src, dst);
    k_layer2  <<<gRows, TB>>>(W2, b1);
    k_scatter <<<gScat, TB>>>(src, dst);
    k_final   <<<gRows, TB>>>(Wc, b2, bc, out);
}